// round 1
// baseline (speedup 1.0000x reference)
#include <cuda_runtime.h>
#include <cstdint>

#define D_MODEL 1024
#define NHEAD 16
#define DK 64
#define BATCH 4
#define SEQ 2048
#define M_ROWS (BATCH * SEQ)          // 8192
#define MASK_WORDS (SEQ / 32)         // 64 words per row
#define NEGV -100000000000.0f

// ---------------- scratch (device globals; no allocations allowed) -------
__device__ float g_Q[M_ROWS * D_MODEL];     // 32 MB
__device__ float g_K[M_ROWS * D_MODEL];     // 32 MB
__device__ float g_V[M_ROWS * D_MODEL];     // 32 MB
__device__ float g_ctx[M_ROWS * D_MODEL];   // 32 MB
__device__ unsigned g_mbits[BATCH * SEQ * MASK_WORDS];  // 2 MB

// ---------------- mask bit-pack: 67MB int32 -> 2MB bits ------------------
__global__ void pack_mask_kernel(const int* __restrict__ mask,
                                 unsigned* __restrict__ bits) {
    int idx = blockIdx.x * blockDim.x + threadIdx.x;  // one int per thread
    int v = mask[idx];
    unsigned ball = __ballot_sync(0xffffffffu, v != 0);
    if ((threadIdx.x & 31) == 0) bits[idx >> 5] = ball;
}

// ---------------- fp32 GEMM: C[M,1024] = A[M,1024] @ W[1024,1024] + b ----
// 128x128 tile, BK=16, 256 threads, 8x8 micro-tile (cols split 2x float4).
__global__ __launch_bounds__(256) void gemm_bias_kernel(
    const float* __restrict__ A, const float* __restrict__ W,
    const float* __restrict__ bias, float* __restrict__ C) {
    __shared__ float As[16][128];   // transposed A tile: [k][row]
    __shared__ float Bs[16][128];   // [k][col]

    const int tid = threadIdx.x;
    const int tr = tid >> 4;   // 0..15 (row group, 8 rows each)
    const int tc = tid & 15;   // 0..15 (col group, 4+4 split cols)
    const int rowBase = blockIdx.y * 128;
    const int colBase = blockIdx.x * 128;

    float acc[8][8];
#pragma unroll
    for (int i = 0; i < 8; i++)
#pragma unroll
        for (int j = 0; j < 8; j++) acc[i][j] = 0.0f;

    const float* Ap = A + (size_t)rowBase * D_MODEL;
    const float* Wp = W + colBase;

    for (int k0 = 0; k0 < D_MODEL; k0 += 16) {
#pragma unroll
        for (int i = 0; i < 2; i++) {
            int idx = tid + i * 256;            // 0..511
            // A tile: 128 rows x 16 cols
            int r  = idx >> 2;                  // 0..127
            int c4 = (idx & 3) << 2;            // 0,4,8,12
            float4 va = *(const float4*)(Ap + (size_t)r * D_MODEL + k0 + c4);
            As[c4 + 0][r] = va.x; As[c4 + 1][r] = va.y;
            As[c4 + 2][r] = va.z; As[c4 + 3][r] = va.w;
            // W tile: 16 rows x 128 cols
            int rb  = idx >> 5;                 // 0..15
            int cb4 = (idx & 31) << 2;          // 0..124
            *(float4*)&Bs[rb][cb4] =
                *(const float4*)(Wp + (size_t)(k0 + rb) * D_MODEL + cb4);
        }
        __syncthreads();

#pragma unroll
        for (int k = 0; k < 16; k++) {
            float ar[8], br[8];
            *(float4*)&ar[0] = *(const float4*)&As[k][tr * 8];
            *(float4*)&ar[4] = *(const float4*)&As[k][tr * 8 + 4];
            *(float4*)&br[0] = *(const float4*)&Bs[k][tc * 4];
            *(float4*)&br[4] = *(const float4*)&Bs[k][64 + tc * 4];
#pragma unroll
            for (int i = 0; i < 8; i++)
#pragma unroll
                for (int j = 0; j < 8; j++)
                    acc[i][j] = fmaf(ar[i], br[j], acc[i][j]);
        }
        __syncthreads();
    }

    // epilogue: bias + store (two float4 per row)
    float b0[4], b1[4];
#pragma unroll
    for (int j = 0; j < 4; j++) {
        b0[j] = bias[colBase + tc * 4 + j];
        b1[j] = bias[colBase + 64 + tc * 4 + j];
    }
#pragma unroll
    for (int i = 0; i < 8; i++) {
        int row = rowBase + tr * 8 + i;
        float4 o0, o1;
        o0.x = acc[i][0] + b0[0]; o0.y = acc[i][1] + b0[1];
        o0.z = acc[i][2] + b0[2]; o0.w = acc[i][3] + b0[3];
        o1.x = acc[i][4] + b1[0]; o1.y = acc[i][5] + b1[1];
        o1.z = acc[i][6] + b1[2]; o1.w = acc[i][7] + b1[3];
        *(float4*)(C + (size_t)row * D_MODEL + colBase + tc * 4) = o0;
        *(float4*)(C + (size_t)row * D_MODEL + colBase + 64 + tc * 4) = o1;
    }
}

// ---------------- fused attention (flash-style, fp32) --------------------
// One block = (b, h, 64-row q tile). 256 threads: 16 row-groups x 16 col-groups,
// each thread owns 4x4 (rows rg+16a, cols cgp+16c) of a 64x64 tile.
#define SMEM_ATTN (4 * 64 * 68 * 4)

__global__ __launch_bounds__(256) void attn_kernel(
    const float* __restrict__ Q, const float* __restrict__ K,
    const float* __restrict__ V, const unsigned* __restrict__ mbits,
    float* __restrict__ ctx) {
    extern __shared__ float sm[];
    float* Qs = sm;                // [64][68]  (row r, dim d)
    float* Ks = sm + 64 * 68;      // [64][68]  transposed: [d][kc]
    float* Vs = sm + 2 * 64 * 68;  // [64][68]  (kc, d)
    float* Ps = sm + 3 * 64 * 68;  // [64][68]  (r, kc)

    const int tid = threadIdx.x;
    const int rg  = tid >> 4;   // 0..15
    const int cgp = tid & 15;   // 0..15
    const int qt = blockIdx.x, h = blockIdx.y, b = blockIdx.z;
    const int qbase = qt * 64;

    const float* Qb = Q + (size_t)(b * SEQ + qbase) * D_MODEL + h * DK;
    const float* Kb = K + (size_t)(b * SEQ) * D_MODEL + h * DK;
    const float* Vb = V + (size_t)(b * SEQ) * D_MODEL + h * DK;
    const unsigned* mbase = mbits + (size_t)(b * SEQ + qbase) * MASK_WORDS;

    // load Q tile (64 x 64)
#pragma unroll
    for (int i = 0; i < 4; i++) {
        int idx = tid + i * 256;        // 0..1023
        int r = idx >> 4;
        int c4 = (idx & 15) << 2;
        float4 v = *(const float4*)(Qb + (size_t)r * D_MODEL + c4);
        float* dst = Qs + r * 68 + c4;
        dst[0] = v.x; dst[1] = v.y; dst[2] = v.z; dst[3] = v.w;
    }

    float acc[4][4];
#pragma unroll
    for (int a = 0; a < 4; a++)
#pragma unroll
        for (int c = 0; c < 4; c++) acc[a][c] = 0.0f;
    float mrow[4], lrow[4];
#pragma unroll
    for (int a = 0; a < 4; a++) { mrow[a] = -3.0e38f; lrow[a] = 0.0f; }

    __syncthreads();

    for (int jt = 0; jt < 32; jt++) {
        // load K tile (transposed into [d][kc]) and V tile ([kc][d])
#pragma unroll
        for (int i = 0; i < 4; i++) {
            int idx = tid + i * 256;
            int kc = idx >> 4;
            int c4 = (idx & 15) << 2;
            float4 kv = *(const float4*)(Kb + (size_t)(jt * 64 + kc) * D_MODEL + c4);
            Ks[(c4 + 0) * 68 + kc] = kv.x;
            Ks[(c4 + 1) * 68 + kc] = kv.y;
            Ks[(c4 + 2) * 68 + kc] = kv.z;
            Ks[(c4 + 3) * 68 + kc] = kv.w;
            float4 vv = *(const float4*)(Vb + (size_t)(jt * 64 + kc) * D_MODEL + c4);
            float* vd = Vs + kc * 68 + c4;
            vd[0] = vv.x; vd[1] = vv.y; vd[2] = vv.z; vd[3] = vv.w;
        }
        __syncthreads();

        // S = Q K^T
        float s[4][4];
#pragma unroll
        for (int a = 0; a < 4; a++)
#pragma unroll
            for (int c = 0; c < 4; c++) s[a][c] = 0.0f;
#pragma unroll
        for (int d = 0; d < 64; d++) {
            float qv[4], kv[4];
#pragma unroll
            for (int a = 0; a < 4; a++) qv[a] = Qs[(rg + 16 * a) * 68 + d];
#pragma unroll
            for (int c = 0; c < 4; c++) kv[c] = Ks[d * 68 + cgp + 16 * c];
#pragma unroll
            for (int a = 0; a < 4; a++)
#pragma unroll
                for (int c = 0; c < 4; c++)
                    s[a][c] = fmaf(qv[a], kv[c], s[a][c]);
        }

        // mask + scale
        unsigned mw[4][2];
#pragma unroll
        for (int a = 0; a < 4; a++) {
            const unsigned* mr = mbase + (size_t)(rg + 16 * a) * MASK_WORDS + jt * 2;
            mw[a][0] = mr[0];
            mw[a][1] = mr[1];
        }
#pragma unroll
        for (int a = 0; a < 4; a++)
#pragma unroll
            for (int c = 0; c < 4; c++) {
                int kc = cgp + 16 * c;
                unsigned w = mw[a][kc >> 5];
                s[a][c] = ((w >> (kc & 31)) & 1u) ? s[a][c] * 0.125f : NEGV;
            }

        // online softmax per row (16 threads/row = one half-warp)
#pragma unroll
        for (int a = 0; a < 4; a++) {
            float mx = fmaxf(fmaxf(s[a][0], s[a][1]), fmaxf(s[a][2], s[a][3]));
#pragma unroll
            for (int off = 8; off >= 1; off >>= 1)
                mx = fmaxf(mx, __shfl_xor_sync(0xffffffffu, mx, off));
            float mn = fmaxf(mrow[a], mx);
            float scale = __expf(mrow[a] - mn);
            float ls = 0.0f;
#pragma unroll
            for (int c = 0; c < 4; c++) {
                float p = __expf(s[a][c] - mn);
                s[a][c] = p;
                ls += p;
            }
#pragma unroll
            for (int off = 8; off >= 1; off >>= 1)
                ls += __shfl_xor_sync(0xffffffffu, ls, off);
            lrow[a] = lrow[a] * scale + ls;
            mrow[a] = mn;
#pragma unroll
            for (int c = 0; c < 4; c++) acc[a][c] *= scale;
        }

        // stage P
#pragma unroll
        for (int a = 0; a < 4; a++)
#pragma unroll
            for (int c = 0; c < 4; c++)
                Ps[(rg + 16 * a) * 68 + cgp + 16 * c] = s[a][c];
        __syncthreads();

        // acc += P @ V
#pragma unroll
        for (int kc = 0; kc < 64; kc++) {
            float pv[4], vv[4];
#pragma unroll
            for (int a = 0; a < 4; a++) pv[a] = Ps[(rg + 16 * a) * 68 + kc];
#pragma unroll
            for (int c = 0; c < 4; c++) vv[c] = Vs[kc * 68 + cgp + 16 * c];
#pragma unroll
            for (int a = 0; a < 4; a++)
#pragma unroll
                for (int c = 0; c < 4; c++)
                    acc[a][c] = fmaf(pv[a], vv[c], acc[a][c]);
        }
        __syncthreads();
    }

    // normalize + write ctx (B, N, H*DK)
#pragma unroll
    for (int a = 0; a < 4; a++) {
        int row = qbase + rg + 16 * a;
        float inv = 1.0f / lrow[a];
#pragma unroll
        for (int c = 0; c < 4; c++)
            ctx[(size_t)(b * SEQ + row) * D_MODEL + h * DK + cgp + 16 * c] =
                acc[a][c] * inv;
    }
}

// ---------------- launch --------------------------------------------------
extern "C" void kernel_launch(void* const* d_in, const int* in_sizes, int n_in,
                              void* d_out, int out_size) {
    const float* query = (const float*)d_in[0];
    const float* key   = (const float*)d_in[1];
    const float* value = (const float*)d_in[2];
    const int*   mask  = (const int*)d_in[3];
    const float* Wq = (const float*)d_in[4];
    const float* bq = (const float*)d_in[5];
    const float* Wk = (const float*)d_in[6];
    const float* bk = (const float*)d_in[7];
    const float* Wv = (const float*)d_in[8];
    const float* bv = (const float*)d_in[9];
    const float* Wo = (const float*)d_in[10];
    const float* bo = (const float*)d_in[11];
    float* out = (float*)d_out;

    float *Qp, *Kp, *Vp, *Cp;
    unsigned* Mp;
    cudaGetSymbolAddress((void**)&Qp, g_Q);
    cudaGetSymbolAddress((void**)&Kp, g_K);
    cudaGetSymbolAddress((void**)&Vp, g_V);
    cudaGetSymbolAddress((void**)&Cp, g_ctx);
    cudaGetSymbolAddress((void**)&Mp, g_mbits);

    cudaFuncSetAttribute(attn_kernel,
                         cudaFuncAttributeMaxDynamicSharedMemorySize, SMEM_ATTN);

    // 1. pack mask -> bits
    pack_mask_kernel<<<(BATCH * SEQ * SEQ) / 256, 256>>>(mask, Mp);

    // 2. Q/K/V projections
    dim3 gg(D_MODEL / 128, M_ROWS / 128);
    gemm_bias_kernel<<<gg, 256>>>(query, Wq, bq, Qp);
    gemm_bias_kernel<<<gg, 256>>>(key, Wk, bk, Kp);
    gemm_bias_kernel<<<gg, 256>>>(value, Wv, bv, Vp);

    // 3. fused masked attention
    dim3 ga(SEQ / 64, NHEAD, BATCH);
    attn_kernel<<<ga, 256, SMEM_ATTN>>>(Qp, Kp, Vp, Mp, Cp);

    // 4. output projection
    gemm_bias_kernel<<<gg, 256>>>(Cp, Wo, bo, out);
}

// round 5
// speedup vs baseline: 1.3298x; 1.3298x over previous
#include <cuda_runtime.h>
#include <cuda_bf16.h>
#include <cstdint>

#define D_MODEL 1024
#define NHEAD 16
#define DK 64
#define BATCH 4
#define SEQ 2048
#define M_ROWS (BATCH * SEQ)          // 8192
#define MASK_WORDS (SEQ / 32)         // 64 words per row
#define NEGV -100000000000.0f

// ---------------- scratch (device globals; no allocations allowed) -------
__device__ float g_Q[M_ROWS * D_MODEL];     // 32 MB
__device__ float g_K[M_ROWS * D_MODEL];     // 32 MB
__device__ float g_V[M_ROWS * D_MODEL];     // 32 MB
__device__ float g_ctx[M_ROWS * D_MODEL];   // 32 MB
__device__ unsigned g_mbits[BATCH * SEQ * MASK_WORDS];  // 2 MB

// ======================= helpers ==========================================
__device__ __forceinline__ uint32_t smem_u32(const void* p) {
    uint32_t a;
    asm("{ .reg .u64 t; cvta.to.shared.u64 t, %1; cvt.u32.u64 %0, t; }"
        : "=r"(a) : "l"(p));
    return a;
}

// bf16x2 split of a pair of floats: hi (rn) + residual lo (rn)
__device__ __forceinline__ void split2(float x0, float x1,
                                       uint32_t& hi, uint32_t& lo) {
    asm("cvt.rn.bf16x2.f32 %0, %1, %2;" : "=r"(hi) : "f"(x1), "f"(x0));
    __nv_bfloat162 h = *reinterpret_cast<__nv_bfloat162*>(&hi);
    float l0 = x0 - __bfloat162float(h.x);
    float l1 = x1 - __bfloat162float(h.y);
    asm("cvt.rn.bf16x2.f32 %0, %1, %2;" : "=r"(lo) : "f"(l1), "f"(l0));
}

__device__ __forceinline__ void ldsm_x4(uint32_t addr, uint32_t* r) {
    asm volatile("ldmatrix.sync.aligned.m8n8.x4.shared.b16 {%0,%1,%2,%3}, [%4];"
                 : "=r"(r[0]), "=r"(r[1]), "=r"(r[2]), "=r"(r[3]) : "r"(addr));
}
__device__ __forceinline__ void ldsm_x2_trans(uint32_t addr, uint32_t* r) {
    asm volatile("ldmatrix.sync.aligned.m8n8.x2.trans.shared.b16 {%0,%1}, [%2];"
                 : "=r"(r[0]), "=r"(r[1]) : "r"(addr));
}
__device__ __forceinline__ void mma16816(float* d, const uint32_t* a,
                                         const uint32_t* b) {
    asm volatile(
        "mma.sync.aligned.m16n8k16.row.col.f32.bf16.bf16.f32 "
        "{%0,%1,%2,%3}, {%4,%5,%6,%7}, {%8,%9}, {%0,%1,%2,%3};"
        : "+f"(d[0]), "+f"(d[1]), "+f"(d[2]), "+f"(d[3])
        : "r"(a[0]), "r"(a[1]), "r"(a[2]), "r"(a[3]), "r"(b[0]), "r"(b[1]));
}

// ---------------- mask bit-pack: 67MB int32 -> 2MB bits ------------------
__global__ void pack_mask_kernel(const int* __restrict__ mask,
                                 unsigned* __restrict__ bits) {
    int idx = blockIdx.x * blockDim.x + threadIdx.x;
    int v = mask[idx];
    unsigned ball = __ballot_sync(0xffffffffu, v != 0);
    if ((threadIdx.x & 31) == 0) bits[idx >> 5] = ball;
}

// =============== HMMA bf16x2-split GEMM ===================================
// C[8192,1024] = A[8192,1024] @ W[1024,1024] + bias.
// 128x128 CTA tile, BK=32 chunks, 8 warps (2m x 4n), warp tile 64x32.
// smem: A row-major [128][40] bf16 (hi,lo), B [32][136] bf16 (hi,lo), x2 buf.
#define LDA 40
#define LDB 136
#define A_TILE (128 * LDA)          // elems
#define B_TILE (32 * LDB)
#define A_BYTES (A_TILE * 2)        // 10240
#define B_BYTES (B_TILE * 2)        // 8704
#define BUFSET (2 * A_BYTES + 2 * B_BYTES)   // 37888
#define SMEM_GEMM (2 * BUFSET)               // 75776

__global__ __launch_bounds__(256) void gemm_mma_kernel(
    const float* __restrict__ A, const float* __restrict__ W,
    const float* __restrict__ bias, float* __restrict__ C) {
    extern __shared__ char smc[];
    const uint32_t smb = smem_u32(smc);
    const int tid = threadIdx.x;
    const int wid = tid >> 5;
    const int lane = tid & 31;
    const int wm = wid >> 2;        // 0..1
    const int wn = wid & 3;         // 0..3
    const int rowBase = blockIdx.y * 128;
    const int colBase = blockIdx.x * 128;

    // per-thread chunk-load coordinates
    const int ar = tid >> 3;            // A row group (4 tasks: +32)
    const int akq = tid & 7;            // A k-quad
    const int bn4 = (tid & 31) * 4;     // B n offset
    const int bk = tid >> 5;            // B k row (tasks: +8)

    // ldmatrix per-thread base offsets (bytes)
    const uint32_t a_lm = ((uint32_t)(wm * 64 + (lane & 15)) * LDA +
                           (uint32_t)(lane >> 4) * 8) * 2;
    const uint32_t b_lm = ((uint32_t)(lane & 15) * LDB + (uint32_t)wn * 32) * 2;

    float acc[4][4][4];
#pragma unroll
    for (int i = 0; i < 4; i++)
#pragma unroll
        for (int j = 0; j < 4; j++)
#pragma unroll
            for (int k = 0; k < 4; k++) acc[i][j][k] = 0.0f;

    float4 rA[4], rB[4];

    // ---- prologue: fetch chunk 0 ----
#pragma unroll
    for (int i = 0; i < 4; i++) {
        int r = ar + i * 32;
        rA[i] = *(const float4*)(A + (size_t)(rowBase + r) * D_MODEL + akq * 4);
        int kb = bk + i * 8;
        rB[i] = *(const float4*)(W + (size_t)kb * D_MODEL + colBase + bn4);
    }

    for (int c = 0; c < 32; c++) {
        const uint32_t base = smb + (c & 1) * BUFSET;
        const uint32_t ah = base, al = base + A_BYTES;
        const uint32_t bh = base + 2 * A_BYTES, bl = bh + B_BYTES;

        // ---- store staged chunk c into smem buffer (c&1) ----
#pragma unroll
        for (int i = 0; i < 4; i++) {
            uint32_t h01, l01, h23, l23;
            split2(rA[i].x, rA[i].y, h01, l01);
            split2(rA[i].z, rA[i].w, h23, l23);
            uint32_t off = ((uint32_t)(ar + i * 32) * LDA + akq * 4) * 2;
            asm volatile("st.shared.v2.b32 [%0], {%1, %2};" :: "r"(ah + off), "r"(h01), "r"(h23) : "memory");
            asm volatile("st.shared.v2.b32 [%0], {%1, %2};" :: "r"(al + off), "r"(l01), "r"(l23) : "memory");
            split2(rB[i].x, rB[i].y, h01, l01);
            split2(rB[i].z, rB[i].w, h23, l23);
            off = ((uint32_t)(bk + i * 8) * LDB + bn4) * 2;
            asm volatile("st.shared.v2.b32 [%0], {%1, %2};" :: "r"(bh + off), "r"(h01), "r"(h23) : "memory");
            asm volatile("st.shared.v2.b32 [%0], {%1, %2};" :: "r"(bl + off), "r"(l01), "r"(l23) : "memory");
        }
        __syncthreads();

        // ---- prefetch chunk c+1 into registers ----
        if (c + 1 < 32) {
            const int k0 = (c + 1) * 32;
#pragma unroll
            for (int i = 0; i < 4; i++) {
                int r = ar + i * 32;
                rA[i] = *(const float4*)(A + (size_t)(rowBase + r) * D_MODEL + k0 + akq * 4);
                int kb = bk + i * 8;
                rB[i] = *(const float4*)(W + (size_t)(k0 + kb) * D_MODEL + colBase + bn4);
            }
        }

        // ---- MMA over the chunk (2 k16-steps) ----
#pragma unroll
        for (int ks = 0; ks < 2; ks++) {
            uint32_t Ah[4][4], Al[4][4], Bh[4][2], Bl[4][2];
#pragma unroll
            for (int mf = 0; mf < 4; mf++) {
                uint32_t off = a_lm + (uint32_t)mf * (16 * LDA * 2) + ks * 32;
                ldsm_x4(ah + off, Ah[mf]);
                ldsm_x4(al + off, Al[mf]);
            }
#pragma unroll
            for (int nf = 0; nf < 4; nf++) {
                uint32_t off = b_lm + (uint32_t)ks * (16 * LDB * 2) + nf * 16;
                ldsm_x2_trans(bh + off, Bh[nf]);
                ldsm_x2_trans(bl + off, Bl[nf]);
            }
#pragma unroll
            for (int mf = 0; mf < 4; mf++)
#pragma unroll
                for (int nf = 0; nf < 4; nf++) {
                    mma16816(acc[mf][nf], Ah[mf], Bh[nf]);
                    mma16816(acc[mf][nf], Ah[mf], Bl[nf]);
                    mma16816(acc[mf][nf], Al[mf], Bh[nf]);
                }
        }
        __syncthreads();
    }

    // ---- epilogue: bias + store ----
#pragma unroll
    for (int nf = 0; nf < 4; nf++) {
        const int col = colBase + wn * 32 + nf * 8 + (lane & 3) * 2;
        const float b0 = bias[col], b1 = bias[col + 1];
#pragma unroll
        for (int mf = 0; mf < 4; mf++) {
            const int row = rowBase + wm * 64 + mf * 16 + (lane >> 2);
            float2 v0 = {acc[mf][nf][0] + b0, acc[mf][nf][1] + b1};
            float2 v1 = {acc[mf][nf][2] + b0, acc[mf][nf][3] + b1};
            *(float2*)(C + (size_t)row * D_MODEL + col) = v0;
            *(float2*)(C + (size_t)(row + 8) * D_MODEL + col) = v1;
        }
    }
}

// ---------------- fused attention (flash-style, fp32) --------------------
#define SMEM_ATTN (4 * 64 * 68 * 4)

__global__ __launch_bounds__(256) void attn_kernel(
    const float* __restrict__ Q, const float* __restrict__ K,
    const float* __restrict__ V, const unsigned* __restrict__ mbits,
    float* __restrict__ ctx) {
    extern __shared__ float smf[];
    float* Qs = smf;
    float* Ks = smf + 64 * 68;
    float* Vs = smf + 2 * 64 * 68;
    float* Ps = smf + 3 * 64 * 68;

    const int tid = threadIdx.x;
    const int rg  = tid >> 4;
    const int cgp = tid & 15;
    const int qt = blockIdx.x, h = blockIdx.y, b = blockIdx.z;
    const int qbase = qt * 64;

    const float* Qb = Q + (size_t)(b * SEQ + qbase) * D_MODEL + h * DK;
    const float* Kb = K + (size_t)(b * SEQ) * D_MODEL + h * DK;
    const float* Vb = V + (size_t)(b * SEQ) * D_MODEL + h * DK;
    const unsigned* mbase = mbits + (size_t)(b * SEQ + qbase) * MASK_WORDS;

#pragma unroll
    for (int i = 0; i < 4; i++) {
        int idx = tid + i * 256;
        int r = idx >> 4;
        int c4 = (idx & 15) << 2;
        float4 v = *(const float4*)(Qb + (size_t)r * D_MODEL + c4);
        float* dst = Qs + r * 68 + c4;
        dst[0] = v.x; dst[1] = v.y; dst[2] = v.z; dst[3] = v.w;
    }

    float acc[4][4];
#pragma unroll
    for (int a = 0; a < 4; a++)
#pragma unroll
        for (int c = 0; c < 4; c++) acc[a][c] = 0.0f;
    float mrow[4], lrow[4];
#pragma unroll
    for (int a = 0; a < 4; a++) { mrow[a] = -3.0e38f; lrow[a] = 0.0f; }

    __syncthreads();

    for (int jt = 0; jt < 32; jt++) {
#pragma unroll
        for (int i = 0; i < 4; i++) {
            int idx = tid + i * 256;
            int kc = idx >> 4;
            int c4 = (idx & 15) << 2;
            float4 kv = *(const float4*)(Kb + (size_t)(jt * 64 + kc) * D_MODEL + c4);
            Ks[(c4 + 0) * 68 + kc] = kv.x;
            Ks[(c4 + 1) * 68 + kc] = kv.y;
            Ks[(c4 + 2) * 68 + kc] = kv.z;
            Ks[(c4 + 3) * 68 + kc] = kv.w;
            float4 vv = *(const float4*)(Vb + (size_t)(jt * 64 + kc) * D_MODEL + c4);
            float* vd = Vs + kc * 68 + c4;
            vd[0] = vv.x; vd[1] = vv.y; vd[2] = vv.z; vd[3] = vv.w;
        }
        __syncthreads();

        float s[4][4];
#pragma unroll
        for (int a = 0; a < 4; a++)
#pragma unroll
            for (int c = 0; c < 4; c++) s[a][c] = 0.0f;
#pragma unroll
        for (int d = 0; d < 64; d++) {
            float qv[4], kv[4];
#pragma unroll
            for (int a = 0; a < 4; a++) qv[a] = Qs[(rg + 16 * a) * 68 + d];
#pragma unroll
            for (int c = 0; c < 4; c++) kv[c] = Ks[d * 68 + cgp + 16 * c];
#pragma unroll
            for (int a = 0; a < 4; a++)
#pragma unroll
                for (int c = 0; c < 4; c++)
                    s[a][c] = fmaf(qv[a], kv[c], s[a][c]);
        }

        unsigned mw[4][2];
#pragma unroll
        for (int a = 0; a < 4; a++) {
            const unsigned* mr = mbase + (size_t)(rg + 16 * a) * MASK_WORDS + jt * 2;
            mw[a][0] = mr[0];
            mw[a][1] = mr[1];
        }
#pragma unroll
        for (int a = 0; a < 4; a++)
#pragma unroll
            for (int c = 0; c < 4; c++) {
                int kc = cgp + 16 * c;
                unsigned w = mw[a][kc >> 5];
                s[a][c] = ((w >> (kc & 31)) & 1u) ? s[a][c] * 0.125f : NEGV;
            }

#pragma unroll
        for (int a = 0; a < 4; a++) {
            float mx = fmaxf(fmaxf(s[a][0], s[a][1]), fmaxf(s[a][2], s[a][3]));
#pragma unroll
            for (int off = 8; off >= 1; off >>= 1)
                mx = fmaxf(mx, __shfl_xor_sync(0xffffffffu, mx, off));
            float mn = fmaxf(mrow[a], mx);
            float scale = __expf(mrow[a] - mn);
            float ls = 0.0f;
#pragma unroll
            for (int c = 0; c < 4; c++) {
                float p = __expf(s[a][c] - mn);
                s[a][c] = p;
                ls += p;
            }
#pragma unroll
            for (int off = 8; off >= 1; off >>= 1)
                ls += __shfl_xor_sync(0xffffffffu, ls, off);
            lrow[a] = lrow[a] * scale + ls;
            mrow[a] = mn;
#pragma unroll
            for (int c = 0; c < 4; c++) acc[a][c] *= scale;
        }

#pragma unroll
        for (int a = 0; a < 4; a++)
#pragma unroll
            for (int c = 0; c < 4; c++)
                Ps[(rg + 16 * a) * 68 + cgp + 16 * c] = s[a][c];
        __syncthreads();

#pragma unroll
        for (int kc = 0; kc < 64; kc++) {
            float pv[4], vv[4];
#pragma unroll
            for (int a = 0; a < 4; a++) pv[a] = Ps[(rg + 16 * a) * 68 + kc];
#pragma unroll
            for (int c = 0; c < 4; c++) vv[c] = Vs[kc * 68 + cgp + 16 * c];
#pragma unroll
            for (int a = 0; a < 4; a++)
#pragma unroll
                for (int c = 0; c < 4; c++)
                    acc[a][c] = fmaf(pv[a], vv[c], acc[a][c]);
        }
        __syncthreads();
    }

#pragma unroll
    for (int a = 0; a < 4; a++) {
        int row = qbase + rg + 16 * a;
        float inv = 1.0f / lrow[a];
#pragma unroll
        for (int c = 0; c < 4; c++)
            ctx[(size_t)(b * SEQ + row) * D_MODEL + h * DK + cgp + 16 * c] =
                acc[a][c] * inv;
    }
}

// ---------------- launch --------------------------------------------------
extern "C" void kernel_launch(void* const* d_in, const int* in_sizes, int n_in,
                              void* d_out, int out_size) {
    const float* query = (const float*)d_in[0];
    const float* key   = (const float*)d_in[1];
    const float* value = (const float*)d_in[2];
    const int*   mask  = (const int*)d_in[3];
    const float* Wq = (const float*)d_in[4];
    const float* bq = (const float*)d_in[5];
    const float* Wk = (const float*)d_in[6];
    const float* bk = (const float*)d_in[7];
    const float* Wv = (const float*)d_in[8];
    const float* bv = (const float*)d_in[9];
    const float* Wo = (const float*)d_in[10];
    const float* bo = (const float*)d_in[11];
    float* out = (float*)d_out;

    float *Qp, *Kp, *Vp, *Cp;
    unsigned* Mp;
    cudaGetSymbolAddress((void**)&Qp, g_Q);
    cudaGetSymbolAddress((void**)&Kp, g_K);
    cudaGetSymbolAddress((void**)&Vp, g_V);
    cudaGetSymbolAddress((void**)&Cp, g_ctx);
    cudaGetSymbolAddress((void**)&Mp, g_mbits);

    cudaFuncSetAttribute(gemm_mma_kernel,
                         cudaFuncAttributeMaxDynamicSharedMemorySize, SMEM_GEMM);
    cudaFuncSetAttribute(attn_kernel,
                         cudaFuncAttributeMaxDynamicSharedMemorySize, SMEM_ATTN);

    // 1. pack mask -> bits
    pack_mask_kernel<<<(BATCH * SEQ * SEQ) / 256, 256>>>(mask, Mp);

    // 2. Q/K/V projections (HMMA bf16x2 split)
    dim3 gg(D_MODEL / 128, M_ROWS / 128);
    gemm_mma_kernel<<<gg, 256, SMEM_GEMM>>>(query, Wq, bq, Qp);
    gemm_mma_kernel<<<gg, 256, SMEM_GEMM>>>(key, Wk, bk, Kp);
    gemm_mma_kernel<<<gg, 256, SMEM_GEMM>>>(value, Wv, bv, Vp);

    // 3. fused masked attention
    dim3 ga(SEQ / 64, NHEAD, BATCH);
    attn_kernel<<<ga, 256, SMEM_ATTN>>>(Qp, Kp, Vp, Mp, Cp);

    // 4. output projection
    gemm_mma_kernel<<<gg, 256, SMEM_GEMM>>>(Cp, Wo, bo, out);
}